// round 1
// baseline (speedup 1.0000x reference)
#include <cuda_runtime.h>
#include <math.h>

#define B_ 8
#define L_ 2048
#define H_ 256

// ---------------- scratch (device globals; no allocation allowed) ----------
__device__ float d_Wh[B_ * L_ * H_];                  // 16.8 MB
__device__ float d_S[33554432];                       // B*L*L = 8*2048*2048, 128 MiB
__device__ float d_C[B_ * L_ * H_];                   // 16.8 MB
__device__ float d_M[B_ * L_];
__device__ float d_ID[B_ * L_];

// ---------------------------------------------------------------------------
// NT SGEMM: C[m,n] = sum_k A[m*lda+k] * B[n*ldb+k]
// 128x128 tile, TK=8, 256 threads, 8x8 microtile. All dims multiples of 128/8.
// ---------------------------------------------------------------------------
__global__ __launch_bounds__(256)
void sgemm_nt(const float* __restrict__ Ag, const float* __restrict__ Bg,
              float* __restrict__ Cg, int K, int lda, int ldb, int ldc,
              long sA, long sB, long sC)
{
    const float* A = Ag + (long)blockIdx.z * sA;
    const float* Bp = Bg + (long)blockIdx.z * sB;
    float* C = Cg + (long)blockIdx.z * sC;

    __shared__ float As[8][128];
    __shared__ float Bs[8][128];

    const int tid = threadIdx.x;
    const int tx = tid & 15, ty = tid >> 4;
    const int mT = blockIdx.y * 128, nT = blockIdx.x * 128;
    const int lr = tid >> 1, lc = (tid & 1) * 4;

    float acc[8][8] = {};

    const float* aPtr = A + (long)(mT + lr) * lda + lc;
    const float* bPtr = Bp + (long)(nT + lr) * ldb + lc;

    for (int kt = 0; kt < K; kt += 8) {
        float4 av = *(const float4*)(aPtr + kt);
        float4 bv = *(const float4*)(bPtr + kt);
        As[lc + 0][lr] = av.x; As[lc + 1][lr] = av.y;
        As[lc + 2][lr] = av.z; As[lc + 3][lr] = av.w;
        Bs[lc + 0][lr] = bv.x; Bs[lc + 1][lr] = bv.y;
        Bs[lc + 2][lr] = bv.z; Bs[lc + 3][lr] = bv.w;
        __syncthreads();
        #pragma unroll
        for (int k = 0; k < 8; k++) {
            float a[8], b[8];
            *(float4*)(a)     = *(const float4*)&As[k][ty * 4];
            *(float4*)(a + 4) = *(const float4*)&As[k][64 + ty * 4];
            *(float4*)(b)     = *(const float4*)&Bs[k][tx * 4];
            *(float4*)(b + 4) = *(const float4*)&Bs[k][64 + tx * 4];
            #pragma unroll
            for (int i = 0; i < 8; i++)
                #pragma unroll
                for (int j = 0; j < 8; j++)
                    acc[i][j] = fmaf(a[i], b[j], acc[i][j]);
        }
        __syncthreads();
    }
    #pragma unroll
    for (int i = 0; i < 8; i++) {
        int m = mT + (i < 4 ? ty * 4 + i : 60 + ty * 4 + i);
        float4 v0 = make_float4(acc[i][0], acc[i][1], acc[i][2], acc[i][3]);
        float4 v1 = make_float4(acc[i][4], acc[i][5], acc[i][6], acc[i][7]);
        *(float4*)(C + (long)m * ldc + nT + tx * 4) = v0;
        *(float4*)(C + (long)m * ldc + nT + 64 + tx * 4) = v1;
    }
}

// ---------------------------------------------------------------------------
// NN SGEMM: C[m,n] = sum_k A[m*lda+k] * B[k*ldb+n]
// ---------------------------------------------------------------------------
__global__ __launch_bounds__(256)
void sgemm_nn(const float* __restrict__ Ag, const float* __restrict__ Bg,
              float* __restrict__ Cg, int K, int lda, int ldb, int ldc,
              long sA, long sB, long sC)
{
    const float* A = Ag + (long)blockIdx.z * sA;
    const float* Bp = Bg + (long)blockIdx.z * sB;
    float* C = Cg + (long)blockIdx.z * sC;

    __shared__ float As[8][128];
    __shared__ float Bs[8][128];

    const int tid = threadIdx.x;
    const int tx = tid & 15, ty = tid >> 4;
    const int mT = blockIdx.y * 128, nT = blockIdx.x * 128;
    const int lr = tid >> 1, lc = (tid & 1) * 4;
    const int br = tid >> 5, bc = (tid & 31) * 4;

    float acc[8][8] = {};

    const float* aPtr = A + (long)(mT + lr) * lda + lc;

    for (int kt = 0; kt < K; kt += 8) {
        float4 av = *(const float4*)(aPtr + kt);
        float4 bv = *(const float4*)(Bp + (long)(kt + br) * ldb + nT + bc);
        As[lc + 0][lr] = av.x; As[lc + 1][lr] = av.y;
        As[lc + 2][lr] = av.z; As[lc + 3][lr] = av.w;
        *(float4*)&Bs[br][bc] = bv;
        __syncthreads();
        #pragma unroll
        for (int k = 0; k < 8; k++) {
            float a[8], b[8];
            *(float4*)(a)     = *(const float4*)&As[k][ty * 4];
            *(float4*)(a + 4) = *(const float4*)&As[k][64 + ty * 4];
            *(float4*)(b)     = *(const float4*)&Bs[k][tx * 4];
            *(float4*)(b + 4) = *(const float4*)&Bs[k][64 + tx * 4];
            #pragma unroll
            for (int i = 0; i < 8; i++)
                #pragma unroll
                for (int j = 0; j < 8; j++)
                    acc[i][j] = fmaf(a[i], b[j], acc[i][j]);
        }
        __syncthreads();
    }
    #pragma unroll
    for (int i = 0; i < 8; i++) {
        int m = mT + (i < 4 ? ty * 4 + i : 60 + ty * 4 + i);
        float4 v0 = make_float4(acc[i][0], acc[i][1], acc[i][2], acc[i][3]);
        float4 v1 = make_float4(acc[i][4], acc[i][5], acc[i][6], acc[i][7]);
        *(float4*)(C + (long)m * ldc + nT + tx * 4) = v0;
        *(float4*)(C + (long)m * ldc + nT + 64 + tx * 4) = v1;
    }
}

// ---------------------------------------------------------------------------
// Column softmax stats over axis i of S[b,i,j]: m_j = max_i, D_j = sum_i exp.
// Block: 256 threads = 32 columns x 8 i-chunks. Online (streaming) update.
// ---------------------------------------------------------------------------
__global__ void colstats(const float* __restrict__ S,
                         float* __restrict__ Mo, float* __restrict__ IDo)
{
    const int b = blockIdx.y;
    const int lane = threadIdx.x & 31;
    const int chunk = threadIdx.x >> 5;       // 0..7
    const int j = blockIdx.x * 32 + lane;

    const float* s = S + (size_t)b * L_ * L_ + j;
    float m = -1e30f, d = 0.f;
    const int i0 = chunk * (L_ / 8);
    #pragma unroll 4
    for (int i = i0; i < i0 + L_ / 8; i++) {
        float x = s[(size_t)i * L_];
        float nm = fmaxf(m, x);
        d = d * __expf(m - nm) + __expf(x - nm);
        m = nm;
    }

    __shared__ float sm[8][32];
    __shared__ float sd[8][32];
    sm[chunk][lane] = m;
    sd[chunk][lane] = d;
    __syncthreads();

    if (chunk == 0) {
        float M = sm[0][lane], D = sd[0][lane];
        #pragma unroll
        for (int c = 1; c < 8; c++) {
            float m2 = sm[c][lane], d2 = sd[c][lane];
            float nm = fmaxf(M, m2);
            D = D * __expf(M - nm) + d2 * __expf(m2 - nm);
            M = nm;
        }
        Mo[b * L_ + j] = M;
        IDo[b * L_ + j] = 1.0f / D;
    }
}

// ---------------------------------------------------------------------------
// In-place: S[b,i,j] <- exp(S - m_j) * invD_j   (attention weights a_t)
// ---------------------------------------------------------------------------
__global__ void normalize_k(float* __restrict__ S,
                            const float* __restrict__ Mo,
                            const float* __restrict__ IDo)
{
    size_t e = ((size_t)blockIdx.x * blockDim.x + threadIdx.x) * 4;
    int j0 = (int)(e & (L_ - 1));
    int b = (int)(e >> 22);                   // L*L = 2^22
    float4 v  = *(const float4*)(S + e);
    float4 mv = *(const float4*)(Mo + b * L_ + j0);
    float4 iv = *(const float4*)(IDo + b * L_ + j0);
    v.x = __expf(v.x - mv.x) * iv.x;
    v.y = __expf(v.y - mv.y) * iv.y;
    v.z = __expf(v.z - mv.z) * iv.z;
    v.w = __expf(v.w - mv.w) * iv.w;
    *(float4*)(S + e) = v;
}

// ---------------------------------------------------------------------------
// Output: out[m,o] = relu(b[o] + g.W1 + c.W2 + (g*c).W3), K = 3*256, NT form.
// A fragments built on the fly per segment; W_out is [256, 768] row-major.
// ---------------------------------------------------------------------------
__global__ __launch_bounds__(256)
void out_kernel(const float* __restrict__ G, const float* __restrict__ Cc,
                const float* __restrict__ W, const float* __restrict__ bias,
                float* __restrict__ O)
{
    __shared__ float As[8][128];
    __shared__ float Bs[8][128];

    const int tid = threadIdx.x;
    const int tx = tid & 15, ty = tid >> 4;
    const int mT = blockIdx.y * 128, nT = blockIdx.x * 128;
    const int lr = tid >> 1, lc = (tid & 1) * 4;

    float acc[8][8] = {};

    const long aOff = (long)(mT + lr) * H_ + lc;
    const float* wRow = W + (long)(nT + lr) * (3 * H_) + lc;

    for (int seg = 0; seg < 3; seg++) {
        for (int kt = 0; kt < H_; kt += 8) {
            float4 av;
            if (seg == 0) {
                av = *(const float4*)(G + aOff + kt);
            } else if (seg == 1) {
                av = *(const float4*)(Cc + aOff + kt);
            } else {
                float4 g4 = *(const float4*)(G + aOff + kt);
                float4 c4 = *(const float4*)(Cc + aOff + kt);
                av = make_float4(g4.x * c4.x, g4.y * c4.y, g4.z * c4.z, g4.w * c4.w);
            }
            float4 bv = *(const float4*)(wRow + seg * H_ + kt);
            As[lc + 0][lr] = av.x; As[lc + 1][lr] = av.y;
            As[lc + 2][lr] = av.z; As[lc + 3][lr] = av.w;
            Bs[lc + 0][lr] = bv.x; Bs[lc + 1][lr] = bv.y;
            Bs[lc + 2][lr] = bv.z; Bs[lc + 3][lr] = bv.w;
            __syncthreads();
            #pragma unroll
            for (int k = 0; k < 8; k++) {
                float a[8], b[8];
                *(float4*)(a)     = *(const float4*)&As[k][ty * 4];
                *(float4*)(a + 4) = *(const float4*)&As[k][64 + ty * 4];
                *(float4*)(b)     = *(const float4*)&Bs[k][tx * 4];
                *(float4*)(b + 4) = *(const float4*)&Bs[k][64 + tx * 4];
                #pragma unroll
                for (int i = 0; i < 8; i++)
                    #pragma unroll
                    for (int j = 0; j < 8; j++)
                        acc[i][j] = fmaf(a[i], b[j], acc[i][j]);
            }
            __syncthreads();
        }
    }

    const int c0 = nT + tx * 4, c1 = nT + 64 + tx * 4;
    float4 b0 = *(const float4*)(bias + c0);
    float4 b1 = *(const float4*)(bias + c1);
    #pragma unroll
    for (int i = 0; i < 8; i++) {
        int m = mT + (i < 4 ? ty * 4 + i : 60 + ty * 4 + i);
        float4 v0 = make_float4(fmaxf(acc[i][0] + b0.x, 0.f),
                                fmaxf(acc[i][1] + b0.y, 0.f),
                                fmaxf(acc[i][2] + b0.z, 0.f),
                                fmaxf(acc[i][3] + b0.w, 0.f));
        float4 v1 = make_float4(fmaxf(acc[i][4] + b1.x, 0.f),
                                fmaxf(acc[i][5] + b1.y, 0.f),
                                fmaxf(acc[i][6] + b1.z, 0.f),
                                fmaxf(acc[i][7] + b1.w, 0.f));
        *(float4*)(O + (long)m * H_ + c0) = v0;
        *(float4*)(O + (long)m * H_ + c1) = v1;
    }
}

// ---------------------------------------------------------------------------
extern "C" void kernel_launch(void* const* d_in, const int* in_sizes, int n_in,
                              void* d_out, int out_size)
{
    const float* g     = (const float*)d_in[0];
    const float* WP    = (const float*)d_in[1];
    const float* W_out = (const float*)d_in[2];
    const float* b_out = (const float*)d_in[3];
    float* out = (float*)d_out;

    float *Wh, *S, *C, *M, *ID;
    cudaGetSymbolAddress((void**)&Wh, d_Wh);
    cudaGetSymbolAddress((void**)&S,  d_S);
    cudaGetSymbolAddress((void**)&C,  d_C);
    cudaGetSymbolAddress((void**)&M,  d_M);
    cudaGetSymbolAddress((void**)&ID, d_ID);

    // 1) Wh = g @ WP^T : M=16384, N=256, K=256
    sgemm_nt<<<dim3(H_ / 128, (B_ * L_) / 128, 1), 256>>>(
        g, WP, Wh, H_, H_, H_, H_, 0, 0, 0);

    // 2) S[b] = Wh[b] @ g[b]^T : per-batch 2048x2048x256
    sgemm_nt<<<dim3(L_ / 128, L_ / 128, B_), 256>>>(
        Wh, g, S, H_, H_, H_, L_,
        (long)L_ * H_, (long)L_ * H_, (long)L_ * L_);

    // 3) column stats (softmax over axis i)
    colstats<<<dim3(L_ / 32, B_), 256>>>(S, M, ID);

    // 4) S <- exp(S - m_j) * invD_j
    normalize_k<<<(B_ * L_ * (L_ / 4)) / 256, 256>>>(S, M, ID);

    // 5) C[b] = A[b] @ g[b] : 2048x256x2048 (NN)
    sgemm_nn<<<dim3(H_ / 128, L_ / 128, B_), 256>>>(
        S, g, C, L_, L_, H_, H_,
        (long)L_ * L_, (long)L_ * H_, (long)L_ * H_);

    // 6) out = relu(cat(g,c,g*c) @ W_out^T + b)
    out_kernel<<<dim3(H_ / 128, (B_ * L_) / 128, 1), 256>>>(
        g, C, W_out, b_out, out);
}

// round 4
// speedup vs baseline: 3.0843x; 3.0843x over previous
#include <cuda_runtime.h>
#include <cuda_bf16.h>
#include <cstdint>
#include <math.h>

#define B_ 8
#define L_ 2048
#define H_ 256

// ======================= PTX helpers (baseline ISA only) ===================
__device__ __forceinline__ uint32_t smem_u32(const void* p) {
    uint32_t a;
    asm("{ .reg .u64 t; cvta.to.shared.u64 t, %1; cvt.u32.u64 %0, t; }" : "=r"(a) : "l"(p));
    return a;
}
#define CP_ASYNC16(dst, src) \
    asm volatile("cp.async.cg.shared.global [%0], [%1], 16;" :: "r"(dst), "l"(src) : "memory")
#define CP_COMMIT() asm volatile("cp.async.commit_group;" ::: "memory")
#define CP_WAIT1()  asm volatile("cp.async.wait_group 1;" ::: "memory")
#define CP_WAIT0()  asm volatile("cp.async.wait_group 0;" ::: "memory")

#define LDSM_X4(r0, r1, r2, r3, a) \
    asm volatile("ldmatrix.sync.aligned.m8n8.x4.shared.b16 {%0,%1,%2,%3}, [%4];" \
        : "=r"(r0), "=r"(r1), "=r"(r2), "=r"(r3) : "r"(a))
#define LDSM_X2(r0, r1, a) \
    asm volatile("ldmatrix.sync.aligned.m8n8.x2.shared.b16 {%0,%1}, [%2];" \
        : "=r"(r0), "=r"(r1) : "r"(a))

#define MMA_BF16(d, a, b) \
    asm volatile("mma.sync.aligned.m16n8k16.row.col.f32.bf16.bf16.f32 " \
        "{%0,%1,%2,%3}, {%4,%5,%6,%7}, {%8,%9}, {%0,%1,%2,%3};" \
        : "+f"((d)[0]), "+f"((d)[1]), "+f"((d)[2]), "+f"((d)[3]) \
        : "r"((a)[0]), "r"((a)[1]), "r"((a)[2]), "r"((a)[3]), "r"((b)[0]), "r"((b)[1]))

__device__ __forceinline__ uint32_t swz(uint32_t o) { return o ^ ((o >> 3) & 0x70); }

// ======================= scratch (device globals) ==========================
__device__ float           d_S[(size_t)B_ * L_ * L_];        // 128 MB
__device__ __nv_bfloat16   d_aHi[(size_t)B_ * L_ * L_];      // 64 MB
__device__ __nv_bfloat16   d_aLo[(size_t)B_ * L_ * L_];      // 64 MB
__device__ __nv_bfloat16   d_gHi[B_ * L_ * H_], d_gLo[B_ * L_ * H_];
__device__ __nv_bfloat16   d_gTHi[B_ * H_ * L_], d_gTLo[B_ * H_ * L_];
__device__ __nv_bfloat16   d_WhHi[B_ * L_ * H_], d_WhLo[B_ * L_ * H_];
__device__ __nv_bfloat16   d_WPHi[H_ * H_], d_WPLo[H_ * H_];
__device__ __nv_bfloat16   d_WoHi[H_ * 3 * H_], d_WoLo[H_ * 3 * H_];
__device__ __nv_bfloat16   d_AcatHi[(size_t)B_ * L_ * 3 * H_], d_AcatLo[(size_t)B_ * L_ * 3 * H_];
__device__ float           d_C[B_ * L_ * H_];
__device__ float           d_M[B_ * L_], d_ID[B_ * L_];

__device__ __forceinline__ void split1(float x, __nv_bfloat16& h, __nv_bfloat16& l) {
    h = __float2bfloat16(x);
    l = __float2bfloat16(x - __bfloat162float(h));
}

// ======================= HMMA split-bf16 NT GEMM ===========================
// D[m,n] = sum_k (Ahi+Alo)[m,k]*(Bhi+Blo)[n,k]  via 3 passes HH+HL+LH.
// CTA tile 128x128, K-chunk 64, 256 threads = 8 warps (2 M x 4 N, 64x32 warp
// tile). Tiles in SMEM: K-major 128 rows x 128B, SW128 swizzle.
// Double-buffered cp.async: stage = {Ahi,Alo,Bhi,Blo} 16KB each = 64KB.
static constexpr int GEMM_SMEM = 2 * 65536;

__device__ __forceinline__ void tile_async(const __nv_bfloat16* __restrict__ src, int ld,
                                           uint32_t dstBase, int tid) {
    #pragma unroll
    for (int s = 0; s < 4; s++) {
        int slot = tid + s * 256;
        int row = slot >> 3;
        int cb = (slot & 7) * 16;
        const char* g = (const char*)src + (size_t)row * ld * 2 + cb;
        CP_ASYNC16(dstBase + swz(row * 128 + cb), g);
    }
}

// MODE 0: fp32 store | MODE 1: split bf16 store | MODE 2: bias+relu fp32
template <int MODE>
__global__ __launch_bounds__(256)
void mma_gemm(const __nv_bfloat16* __restrict__ Ahi, const __nv_bfloat16* __restrict__ Alo,
              const __nv_bfloat16* __restrict__ Bhi, const __nv_bfloat16* __restrict__ Blo,
              float* __restrict__ Cf, __nv_bfloat16* __restrict__ Chi, __nv_bfloat16* __restrict__ Clo,
              const float* __restrict__ bias,
              int K, int lda, int ldb, int ldc, long sA, long sB, long sC)
{
    extern __shared__ char smem[];
    const uint32_t sb = smem_u32(smem);
    const int tid = threadIdx.x;
    const int lane = tid & 31, wid = tid >> 5;
    const int wM = wid >> 2, wN = wid & 3;          // 2 x 4 warp grid
    const int mT = blockIdx.y * 128, nT = blockIdx.x * 128;
    const long z = blockIdx.z;

    const __nv_bfloat16* Ah = Ahi + z * sA + (long)mT * lda;
    const __nv_bfloat16* Al = Alo + z * sA + (long)mT * lda;
    const __nv_bfloat16* Bh = Bhi + z * sB + (long)nT * ldb;
    const __nv_bfloat16* Bl = Blo + z * sB + (long)nT * ldb;

    const int NC = K >> 6;

    // issue chunk 0 into buffer 0
    tile_async(Ah, lda, sb,          tid);
    tile_async(Al, lda, sb + 16384,  tid);
    tile_async(Bh, ldb, sb + 32768,  tid);
    tile_async(Bl, ldb, sb + 49152,  tid);
    CP_COMMIT();

    float acc[4][4][4] = {};

    // ldmatrix lane addressing components
    const int aRow = lane & 15;                 // + wM*64 + mi*16
    const int aColB = (lane >> 4) * 16;         // + ks*32
    const int bRow = lane & 7;                  // + wN*32 + ni*8
    const int bColB = ((lane >> 3) & 1) * 16;   // + ks*32

    for (int c = 0; c < NC; c++) {
        if (c + 1 < NC) {
            const uint32_t o1 = sb + ((c + 1) & 1) * 65536;
            const int k1 = (c + 1) * 64;
            tile_async(Ah + k1, lda, o1,          tid);
            tile_async(Al + k1, lda, o1 + 16384,  tid);
            tile_async(Bh + k1, ldb, o1 + 32768,  tid);
            tile_async(Bl + k1, ldb, o1 + 49152,  tid);
            CP_COMMIT();
            CP_WAIT1();
        } else {
            CP_WAIT0();
        }
        __syncthreads();

        const uint32_t o = sb + (c & 1) * 65536;
        const uint32_t aB = o, alB = o + 16384, bB = o + 32768, blB = o + 49152;

        #pragma unroll
        for (int ks = 0; ks < 4; ks++) {
            const int kb = ks * 32;
            uint32_t rah[4][4], ral[4][4], rbh[4][2], rbl[4][2];
            #pragma unroll
            for (int mi = 0; mi < 4; mi++) {
                uint32_t off = swz((uint32_t)(wM * 64 + mi * 16 + aRow) * 128 + kb + aColB);
                LDSM_X4(rah[mi][0], rah[mi][1], rah[mi][2], rah[mi][3], aB + off);
                LDSM_X4(ral[mi][0], ral[mi][1], ral[mi][2], ral[mi][3], alB + off);
            }
            #pragma unroll
            for (int ni = 0; ni < 4; ni++) {
                uint32_t off = swz((uint32_t)(wN * 32 + ni * 8 + bRow) * 128 + kb + bColB);
                LDSM_X2(rbh[ni][0], rbh[ni][1], bB + off);
                LDSM_X2(rbl[ni][0], rbl[ni][1], blB + off);
            }
            #pragma unroll
            for (int mi = 0; mi < 4; mi++)
                #pragma unroll
                for (int ni = 0; ni < 4; ni++) {
                    MMA_BF16(acc[mi][ni], rah[mi], rbh[ni]);
                    MMA_BF16(acc[mi][ni], rah[mi], rbl[ni]);
                    MMA_BF16(acc[mi][ni], ral[mi], rbh[ni]);
                }
        }
        __syncthreads();
    }

    // ---------------- epilogue ----------------
    const int rBase = mT + wM * 64 + (lane >> 2);
    const int cBase = nT + wN * 32 + (lane & 3) * 2;
    #pragma unroll
    for (int mi = 0; mi < 4; mi++) {
        #pragma unroll
        for (int ni = 0; ni < 4; ni++) {
            const int r0 = rBase + mi * 16;
            const int c0 = cBase + ni * 8;
            float* p = acc[mi][ni];
            if (MODE == 0) {
                float* dst = Cf + z * sC;
                *(float2*)(dst + (size_t)r0 * ldc + c0) = make_float2(p[0], p[1]);
                *(float2*)(dst + (size_t)(r0 + 8) * ldc + c0) = make_float2(p[2], p[3]);
            } else if (MODE == 1) {
                #pragma unroll
                for (int hh = 0; hh < 2; hh++) {
                    __nv_bfloat16 h0, l0, h1, l1;
                    split1(p[hh * 2 + 0], h0, l0);
                    split1(p[hh * 2 + 1], h1, l1);
                    uint32_t ph = ((uint32_t)*(uint16_t*)&h1 << 16) | *(uint16_t*)&h0;
                    uint32_t pl = ((uint32_t)*(uint16_t*)&l1 << 16) | *(uint16_t*)&l0;
                    size_t idx = z * sC + (size_t)(r0 + hh * 8) * ldc + c0;
                    *(uint32_t*)(Chi + idx) = ph;
                    *(uint32_t*)(Clo + idx) = pl;
                }
            } else {
                float2 bv = *(const float2*)(bias + c0);
                float* dst = Cf + z * sC;
                *(float2*)(dst + (size_t)r0 * ldc + c0) =
                    make_float2(fmaxf(p[0] + bv.x, 0.f), fmaxf(p[1] + bv.y, 0.f));
                *(float2*)(dst + (size_t)(r0 + 8) * ldc + c0) =
                    make_float2(fmaxf(p[2] + bv.x, 0.f), fmaxf(p[3] + bv.y, 0.f));
            }
        }
    }
}

// ======================= small prep/softmax kernels ========================
__global__ void split_k(const float* __restrict__ x, __nv_bfloat16* __restrict__ hi,
                        __nv_bfloat16* __restrict__ lo, int n4)
{
    for (int i = blockIdx.x * blockDim.x + threadIdx.x; i < n4; i += gridDim.x * blockDim.x) {
        float4 v = ((const float4*)x)[i];
        __nv_bfloat16 h[4], l[4];
        split1(v.x, h[0], l[0]); split1(v.y, h[1], l[1]);
        split1(v.z, h[2], l[2]); split1(v.w, h[3], l[3]);
        ((uint2*)hi)[i] = *(uint2*)h;
        ((uint2*)lo)[i] = *(uint2*)l;
    }
}

__global__ void transpose_split(const float* __restrict__ G,
                                __nv_bfloat16* __restrict__ Thi, __nv_bfloat16* __restrict__ Tlo)
{
    __shared__ float t[32][33];
    const int j0 = blockIdx.x * 32, h0 = blockIdx.y * 32, b = blockIdx.z;
    const float* Gb = G + (size_t)b * L_ * H_;
    #pragma unroll
    for (int r = 0; r < 4; r++) {
        int row = threadIdx.y + r * 8;
        t[row][threadIdx.x] = Gb[(size_t)(j0 + row) * H_ + h0 + threadIdx.x];
    }
    __syncthreads();
    __nv_bfloat16* Th = Thi + (size_t)b * H_ * L_;
    __nv_bfloat16* Tl = Tlo + (size_t)b * H_ * L_;
    #pragma unroll
    for (int r = 0; r < 4; r++) {
        int hr = threadIdx.y + r * 8;
        float x = t[threadIdx.x][hr];
        __nv_bfloat16 h, l; split1(x, h, l);
        Th[(size_t)(h0 + hr) * L_ + j0 + threadIdx.x] = h;
        Tl[(size_t)(h0 + hr) * L_ + j0 + threadIdx.x] = l;
    }
}

__global__ void colstats(const float* __restrict__ S,
                         float* __restrict__ Mo, float* __restrict__ IDo)
{
    const int b = blockIdx.y;
    const int lane = threadIdx.x & 31;
    const int chunk = threadIdx.x >> 5;
    const int j = blockIdx.x * 32 + lane;

    const float* s = S + (size_t)b * L_ * L_ + j;
    float m = -1e30f, d = 0.f;
    const int i0 = chunk * (L_ / 8);
    #pragma unroll 4
    for (int i = i0; i < i0 + L_ / 8; i++) {
        float x = s[(size_t)i * L_];
        float nm = fmaxf(m, x);
        d = d * __expf(m - nm) + __expf(x - nm);
        m = nm;
    }
    __shared__ float sm[8][32], sd[8][32];
    sm[chunk][lane] = m; sd[chunk][lane] = d;
    __syncthreads();
    if (chunk == 0) {
        float M = sm[0][lane], D = sd[0][lane];
        #pragma unroll
        for (int c = 1; c < 8; c++) {
            float m2 = sm[c][lane], d2 = sd[c][lane];
            float nm = fmaxf(M, m2);
            D = D * __expf(M - nm) + d2 * __expf(m2 - nm);
            M = nm;
        }
        Mo[b * L_ + j] = M;
        IDo[b * L_ + j] = 1.0f / D;
    }
}

__global__ void normalize_split(const float* __restrict__ S,
                                const float* __restrict__ Mo, const float* __restrict__ IDo,
                                __nv_bfloat16* __restrict__ aHi, __nv_bfloat16* __restrict__ aLo)
{
    size_t e = ((size_t)blockIdx.x * blockDim.x + threadIdx.x) * 4;
    int j0 = (int)(e & (L_ - 1));
    int b = (int)(e >> 22);
    float4 v  = *(const float4*)(S + e);
    float4 mv = *(const float4*)(Mo + b * L_ + j0);
    float4 iv = *(const float4*)(IDo + b * L_ + j0);
    float p0 = __expf(v.x - mv.x) * iv.x;
    float p1 = __expf(v.y - mv.y) * iv.y;
    float p2 = __expf(v.z - mv.z) * iv.z;
    float p3 = __expf(v.w - mv.w) * iv.w;
    __nv_bfloat16 h[4], l[4];
    split1(p0, h[0], l[0]); split1(p1, h[1], l[1]);
    split1(p2, h[2], l[2]); split1(p3, h[3], l[3]);
    *(uint2*)(aHi + e) = *(uint2*)h;
    *(uint2*)(aLo + e) = *(uint2*)l;
}

__global__ void catprep(const float* __restrict__ G, const float* __restrict__ C,
                        __nv_bfloat16* __restrict__ Ahi, __nv_bfloat16* __restrict__ Alo)
{
    size_t t = (size_t)blockIdx.x * blockDim.x + threadIdx.x;
    int m = (int)(t >> 6);
    int kq = (int)(t & 63) * 4;
    float4 g4 = *(const float4*)(G + (size_t)m * H_ + kq);
    float4 c4 = *(const float4*)(C + (size_t)m * H_ + kq);
    float4 p4 = make_float4(g4.x * c4.x, g4.y * c4.y, g4.z * c4.z, g4.w * c4.w);
    size_t base = (size_t)m * (3 * H_) + kq;
    __nv_bfloat16 h[4], l[4];
    split1(g4.x, h[0], l[0]); split1(g4.y, h[1], l[1]); split1(g4.z, h[2], l[2]); split1(g4.w, h[3], l[3]);
    *(uint2*)(Ahi + base) = *(uint2*)h; *(uint2*)(Alo + base) = *(uint2*)l;
    split1(c4.x, h[0], l[0]); split1(c4.y, h[1], l[1]); split1(c4.z, h[2], l[2]); split1(c4.w, h[3], l[3]);
    *(uint2*)(Ahi + base + H_) = *(uint2*)h; *(uint2*)(Alo + base + H_) = *(uint2*)l;
    split1(p4.x, h[0], l[0]); split1(p4.y, h[1], l[1]); split1(p4.z, h[2], l[2]); split1(p4.w, h[3], l[3]);
    *(uint2*)(Ahi + base + 2 * H_) = *(uint2*)h; *(uint2*)(Alo + base + 2 * H_) = *(uint2*)l;
}

// ===========================================================================
extern "C" void kernel_launch(void* const* d_in, const int* in_sizes, int n_in,
                              void* d_out, int out_size)
{
    const float* g     = (const float*)d_in[0];
    const float* WP    = (const float*)d_in[1];
    const float* W_out = (const float*)d_in[2];
    const float* b_out = (const float*)d_in[3];
    float* out = (float*)d_out;

    float *S, *C, *M, *ID;
    __nv_bfloat16 *aHi, *aLo, *gHi, *gLo, *gTHi, *gTLo, *WhHi, *WhLo;
    __nv_bfloat16 *WPHi, *WPLo, *WoHi, *WoLo, *AcHi, *AcLo;
    cudaGetSymbolAddress((void**)&S, d_S);
    cudaGetSymbolAddress((void**)&C, d_C);
    cudaGetSymbolAddress((void**)&M, d_M);
    cudaGetSymbolAddress((void**)&ID, d_ID);
    cudaGetSymbolAddress((void**)&aHi, d_aHi);   cudaGetSymbolAddress((void**)&aLo, d_aLo);
    cudaGetSymbolAddress((void**)&gHi, d_gHi);   cudaGetSymbolAddress((void**)&gLo, d_gLo);
    cudaGetSymbolAddress((void**)&gTHi, d_gTHi); cudaGetSymbolAddress((void**)&gTLo, d_gTLo);
    cudaGetSymbolAddress((void**)&WhHi, d_WhHi); cudaGetSymbolAddress((void**)&WhLo, d_WhLo);
    cudaGetSymbolAddress((void**)&WPHi, d_WPHi); cudaGetSymbolAddress((void**)&WPLo, d_WPLo);
    cudaGetSymbolAddress((void**)&WoHi, d_WoHi); cudaGetSymbolAddress((void**)&WoLo, d_WoLo);
    cudaGetSymbolAddress((void**)&AcHi, d_AcatHi); cudaGetSymbolAddress((void**)&AcLo, d_AcatLo);

    cudaFuncSetAttribute(mma_gemm<0>, cudaFuncAttributeMaxDynamicSharedMemorySize, GEMM_SMEM);
    cudaFuncSetAttribute(mma_gemm<1>, cudaFuncAttributeMaxDynamicSharedMemorySize, GEMM_SMEM);
    cudaFuncSetAttribute(mma_gemm<2>, cudaFuncAttributeMaxDynamicSharedMemorySize, GEMM_SMEM);

    // 0) split inputs to hi/lo bf16
    split_k<<<2048, 256>>>(g, gHi, gLo, B_ * L_ * H_ / 4);
    split_k<<<64, 256>>>(WP, WPHi, WPLo, H_ * H_ / 4);
    split_k<<<192, 256>>>(W_out, WoHi, WoLo, H_ * 3 * H_ / 4);
    transpose_split<<<dim3(L_ / 32, H_ / 32, B_), dim3(32, 8)>>>(g, gTHi, gTLo);

    // 1) Wh = g @ WP^T  (16384 x 256 x 256) -> split bf16
    mma_gemm<1><<<dim3(2, 128, 1), 256, GEMM_SMEM>>>(
        gHi, gLo, WPHi, WPLo, nullptr, WhHi, WhLo, nullptr,
        H_, H_, H_, H_, 0, 0, 0);

    // 2) S[b] = Wh[b] @ g[b]^T  (2048 x 2048 x 256 per batch) -> fp32
    mma_gemm<0><<<dim3(16, 16, B_), 256, GEMM_SMEM>>>(
        WhHi, WhLo, gHi, gLo, S, nullptr, nullptr, nullptr,
        H_, H_, H_, L_, (long)L_ * H_, (long)L_ * H_, (long)L_ * L_);

    // 3) column softmax stats (over axis i)
    colstats<<<dim3(L_ / 32, B_), 256>>>(S, M, ID);

    // 4) a = exp(S - m_j) * invD_j -> split bf16
    normalize_split<<<(int)(((size_t)B_ * L_ * (L_ / 4)) / 256), 256>>>(S, M, ID, aHi, aLo);

    // 5) c[b] = a[b] @ g[b] == a @ gT^T  (2048 x 256 x 2048 per batch) -> fp32
    mma_gemm<0><<<dim3(2, 16, B_), 256, GEMM_SMEM>>>(
        aHi, aLo, gTHi, gTLo, C, nullptr, nullptr, nullptr,
        L_, L_, L_, H_, (long)L_ * L_, (long)H_ * L_, (long)L_ * H_);

    // 6) build cat(g, c, g*c) hi/lo
    catprep<<<(B_ * L_ * (H_ / 4)) / 256, 256>>>(g, C, AcHi, AcLo);

    // 7) out = relu(cat @ W_out^T + b)  (16384 x 256 x 768)
    mma_gemm<2><<<dim3(2, 128, 1), 256, GEMM_SMEM>>>(
        AcHi, AcLo, WoHi, WoLo, out, nullptr, nullptr, b_out,
        3 * H_, 3 * H_, 3 * H_, H_, 0, 0, 0);
}

// round 6
// speedup vs baseline: 4.5118x; 1.4628x over previous
#include <cuda_runtime.h>
#include <cuda_bf16.h>
#include <cstdint>
#include <math.h>

#define B_ 8
#define L_ 2048
#define H_ 256

// ======================= PTX helpers (baseline ISA only) ===================
__device__ __forceinline__ uint32_t smem_u32(const void* p) {
    uint32_t a;
    asm("{ .reg .u64 t; cvta.to.shared.u64 t, %1; cvt.u32.u64 %0, t; }" : "=r"(a) : "l"(p));
    return a;
}
#define CP_ASYNC16(dst, src) \
    asm volatile("cp.async.cg.shared.global [%0], [%1], 16;" :: "r"(dst), "l"(src) : "memory")
#define CP_COMMIT() asm volatile("cp.async.commit_group;" ::: "memory")
#define CP_WAIT1()  asm volatile("cp.async.wait_group 1;" ::: "memory")
#define CP_WAIT0()  asm volatile("cp.async.wait_group 0;" ::: "memory")

#define LDSM_X4(r0, r1, r2, r3, a) \
    asm volatile("ldmatrix.sync.aligned.m8n8.x4.shared.b16 {%0,%1,%2,%3}, [%4];" \
        : "=r"(r0), "=r"(r1), "=r"(r2), "=r"(r3) : "r"(a))
#define LDSM_X2(r0, r1, a) \
    asm volatile("ldmatrix.sync.aligned.m8n8.x2.shared.b16 {%0,%1}, [%2];" \
        : "=r"(r0), "=r"(r1) : "r"(a))

#define MMA_BF16(d, a, b) \
    asm volatile("mma.sync.aligned.m16n8k16.row.col.f32.bf16.bf16.f32 " \
        "{%0,%1,%2,%3}, {%4,%5,%6,%7}, {%8,%9}, {%0,%1,%2,%3};" \
        : "+f"((d)[0]), "+f"((d)[1]), "+f"((d)[2]), "+f"((d)[3]) \
        : "r"((a)[0]), "r"((a)[1]), "r"((a)[2]), "r"((a)[3]), "r"((b)[0]), "r"((b)[1]))

__device__ __forceinline__ uint32_t swz(uint32_t o) { return o ^ ((o >> 3) & 0x70); }

// ======================= scratch (device globals) ==========================
__device__ float           d_S[(size_t)B_ * L_ * L_];        // 128 MB
__device__ __nv_bfloat16   d_gHi[B_ * L_ * H_], d_gLo[B_ * L_ * H_];
__device__ __nv_bfloat16   d_gTHi[B_ * H_ * L_], d_gTLo[B_ * H_ * L_];
__device__ __nv_bfloat16   d_WhHi[B_ * L_ * H_], d_WhLo[B_ * L_ * H_];
__device__ __nv_bfloat16   d_WPHi[H_ * H_], d_WPLo[H_ * H_];
__device__ __nv_bfloat16   d_WoHi[H_ * 3 * H_], d_WoLo[H_ * 3 * H_];
__device__ float           d_C[B_ * L_ * H_];
__device__ float           d_M[B_ * L_], d_ID[B_ * L_];
__device__ float           d_Pmax[B_ * 16 * L_], d_Psum[B_ * 16 * L_];   // per-(mTile) partials

__device__ __forceinline__ void split1(float x, __nv_bfloat16& h, __nv_bfloat16& l) {
    h = __float2bfloat16(x);
    l = __float2bfloat16(x - __bfloat162float(h));
}
// pack 4 floats into (hi uint2, lo uint2) of bf16 pairs
__device__ __forceinline__ void pack_split4(float4 v, uint2& hi, uint2& lo) {
    __nv_bfloat16 h[4], l[4];
    split1(v.x, h[0], l[0]); split1(v.y, h[1], l[1]);
    split1(v.z, h[2], l[2]); split1(v.w, h[3], l[3]);
    hi = *(uint2*)h; lo = *(uint2*)l;
}

// ======================= HMMA split-bf16 NT GEMM ===========================
// D[m,n] = sum_k (Ahi+Alo)[m,k]*(Bhi+Blo)[n,k]  via 3 passes HH+HL+LH.
// CTA tile 128x128, K-chunk 64, 8 warps (2M x 4N). SMEM stage (64KB):
//   [0]Ahi [16K]Alo [32K]Bhi [48K]Blo, double buffered (128KB).
// AM: 0 = A pre-split bf16 via cp.async
//     1 = A produced in-kernel: a = exp(S - M_j)*ID_j  (fp32 S, reg-prefetched)
//     2 = A produced in-kernel: cat(g, C, g*C) segments (fp32 g,C)
// EM: 0 = fp32 store | 1 = split-bf16 store | 2 = bias+relu | 3 = fp32 + col stats
static constexpr int GEMM_SMEM = 2 * 65536;

__device__ __forceinline__ void tile_async(const __nv_bfloat16* __restrict__ src, int ld,
                                           uint32_t dstBase, int tid) {
    #pragma unroll
    for (int s = 0; s < 4; s++) {
        int slot = tid + s * 256;
        int row = slot >> 3;
        int cb = (slot & 7) * 16;
        const char* g = (const char*)src + (size_t)row * ld * 2 + cb;
        CP_ASYNC16(dstBase + swz(row * 128 + cb), g);
    }
}

template <int AM, int EM>
__global__ __launch_bounds__(256)
void mma_gemm(const __nv_bfloat16* __restrict__ Ahi, const __nv_bfloat16* __restrict__ Alo,
              const float* __restrict__ Af1, const float* __restrict__ Af2,
              const float* __restrict__ Mst, const float* __restrict__ IDst,
              const __nv_bfloat16* __restrict__ Bhi, const __nv_bfloat16* __restrict__ Blo,
              float* __restrict__ Cf, __nv_bfloat16* __restrict__ Chi, __nv_bfloat16* __restrict__ Clo,
              const float* __restrict__ bias,
              float* __restrict__ Pmax, float* __restrict__ Psum,
              int K, int lda, int ldaF, int ldb, int ldc, long sA, long sB, long sC)
{
    extern __shared__ char smem[];
    const uint32_t sb = smem_u32(smem);
    const int tid = threadIdx.x;
    const int lane = tid & 31, wid = tid >> 5;
    const int wM = wid >> 2, wN = wid & 3;
    const int mT = blockIdx.y * 128, nT = blockIdx.x * 128;
    const long z = blockIdx.z;

    const __nv_bfloat16* Bh = Bhi + z * sB + (long)nT * ldb;
    const __nv_bfloat16* Bl = Blo + z * sB + (long)nT * ldb;
    const int NC = K >> 6;

    // fused A addressing (AM 1/2): thread covers one float4 column group,
    // rows (tid>>4) + s*16, s<8.  c4 = float4 col index in chunk.
    const int c4 = tid & 15;
    const int rA = tid >> 4;
    float4 ra[8];

    const __nv_bfloat16* Ah = nullptr; const __nv_bfloat16* Al = nullptr;
    const float* Sg = nullptr;
    if (AM == 0) {
        Ah = Ahi + z * sA + (long)mT * lda;
        Al = Alo + z * sA + (long)mT * lda;
    } else if (AM == 1) {
        Sg = Af1 + z * sA + (size_t)mT * ldaF;
    }

    // ---- prologue: stage chunk 0 ----
    if (AM == 0) {
        tile_async(Ah, lda, sb,         tid);
        tile_async(Al, lda, sb + 16384, tid);
    } else if (AM == 1) {
        #pragma unroll
        for (int s = 0; s < 8; s++)
            ra[s] = *(const float4*)(Sg + (size_t)(rA + s * 16) * ldaF + c4 * 4);
    }
    tile_async(Bh, ldb, sb + 32768, tid);
    tile_async(Bl, ldb, sb + 49152, tid);
    CP_COMMIT();

    float acc[4][4][4] = {};
    const int aRow = lane & 15;
    const int aColB = (lane >> 4) * 16;
    const int bRow = lane & 7;
    const int bColB = ((lane >> 3) & 1) * 16;

    for (int c = 0; c < NC; c++) {
        const int buf = c & 1;
        const uint32_t o = sb + buf * 65536;

        // ---- produce A(c) into buf for fused modes ----
        if (AM == 1) {
            const int k0 = c * 64;
            float4 mv = *(const float4*)(Mst  + z * L_ + k0 + c4 * 4);
            float4 iv = *(const float4*)(IDst + z * L_ + k0 + c4 * 4);
            #pragma unroll
            for (int s = 0; s < 8; s++) {
                float4 v = ra[s];
                v.x = __expf(v.x - mv.x) * iv.x;
                v.y = __expf(v.y - mv.y) * iv.y;
                v.z = __expf(v.z - mv.z) * iv.z;
                v.w = __expf(v.w - mv.w) * iv.w;
                uint2 hi, lo; pack_split4(v, hi, lo);
                uint32_t off = swz((uint32_t)(rA + s * 16) * 128 + c4 * 8);
                *(uint2*)(smem + buf * 65536 + off) = hi;
                *(uint2*)(smem + buf * 65536 + 16384 + off) = lo;
            }
        } else if (AM == 2) {
            const int k0 = c * 64;
            const int seg = k0 >> 8;
            const int hc = (k0 & 255) + c4 * 4;
            #pragma unroll
            for (int s = 0; s < 8; s++) {
                const size_t mrow = (size_t)(mT + rA + s * 16);
                float4 v;
                if (seg == 0) v = *(const float4*)(Af1 + mrow * ldaF + hc);
                else if (seg == 1) v = *(const float4*)(Af2 + mrow * ldaF + hc);
                else {
                    float4 g4 = *(const float4*)(Af1 + mrow * ldaF + hc);
                    float4 cc = *(const float4*)(Af2 + mrow * ldaF + hc);
                    v = make_float4(g4.x * cc.x, g4.y * cc.y, g4.z * cc.z, g4.w * cc.w);
                }
                uint2 hi, lo; pack_split4(v, hi, lo);
                uint32_t off = swz((uint32_t)(rA + s * 16) * 128 + c4 * 8);
                *(uint2*)(smem + buf * 65536 + off) = hi;
                *(uint2*)(smem + buf * 65536 + 16384 + off) = lo;
            }
        }

        // ---- stage chunk c+1 ----
        if (c + 1 < NC) {
            const uint32_t o1 = sb + ((c + 1) & 1) * 65536;
            const int k1 = (c + 1) * 64;
            if (AM == 0) {
                tile_async(Ah + k1, lda, o1,         tid);
                tile_async(Al + k1, lda, o1 + 16384, tid);
            } else if (AM == 1) {
                #pragma unroll
                for (int s = 0; s < 8; s++)
                    ra[s] = *(const float4*)(Sg + (size_t)(rA + s * 16) * ldaF + k1 + c4 * 4);
            }
            tile_async(Bh + k1, ldb, o1 + 32768, tid);
            tile_async(Bl + k1, ldb, o1 + 49152, tid);
            CP_COMMIT();
            CP_WAIT1();
        } else {
            CP_WAIT0();
        }
        __syncthreads();

        const uint32_t aB = o, alB = o + 16384, bB = o + 32768, blB = o + 49152;
        #pragma unroll
        for (int ks = 0; ks < 4; ks++) {
            const int kb = ks * 32;
            uint32_t rah[4][4], ral[4][4], rbh[4][2], rbl[4][2];
            #pragma unroll
            for (int mi = 0; mi < 4; mi++) {
                uint32_t off = swz((uint32_t)(wM * 64 + mi * 16 + aRow) * 128 + kb + aColB);
                LDSM_X4(rah[mi][0], rah[mi][1], rah[mi][2], rah[mi][3], aB + off);
                LDSM_X4(ral[mi][0], ral[mi][1], ral[mi][2], ral[mi][3], alB + off);
            }
            #pragma unroll
            for (int ni = 0; ni < 4; ni++) {
                uint32_t off = swz((uint32_t)(wN * 32 + ni * 8 + bRow) * 128 + kb + bColB);
                LDSM_X2(rbh[ni][0], rbh[ni][1], bB + off);
                LDSM_X2(rbl[ni][0], rbl[ni][1], blB + off);
            }
            #pragma unroll
            for (int mi = 0; mi < 4; mi++)
                #pragma unroll
                for (int ni = 0; ni < 4; ni++) {
                    MMA_BF16(acc[mi][ni], rah[mi], rbh[ni]);
                    MMA_BF16(acc[mi][ni], rah[mi], rbl[ni]);
                    MMA_BF16(acc[mi][ni], ral[mi], rbh[ni]);
                }
        }
        __syncthreads();
    }

    // ---------------- epilogue: stores ----------------
    const int rBase = mT + wM * 64 + (lane >> 2);
    const int cBase = nT + wN * 32 + (lane & 3) * 2;
    #pragma unroll
    for (int mi = 0; mi < 4; mi++) {
        #pragma unroll
        for (int ni = 0; ni < 4; ni++) {
            const int r0 = rBase + mi * 16;
            const int c0 = cBase + ni * 8;
            float* p = acc[mi][ni];
            if (EM == 0 || EM == 3) {
                float* dst = Cf + z * sC;
                *(float2*)(dst + (size_t)r0 * ldc + c0) = make_float2(p[0], p[1]);
                *(float2*)(dst + (size_t)(r0 + 8) * ldc + c0) = make_float2(p[2], p[3]);
            } else if (EM == 1) {
                #pragma unroll
                for (int hh = 0; hh < 2; hh++) {
                    __nv_bfloat16 h0, l0, h1, l1;
                    split1(p[hh * 2 + 0], h0, l0);
                    split1(p[hh * 2 + 1], h1, l1);
                    uint32_t ph = ((uint32_t)*(uint16_t*)&h1 << 16) | *(uint16_t*)&h0;
                    uint32_t pl = ((uint32_t)*(uint16_t*)&l1 << 16) | *(uint16_t*)&l0;
                    size_t idx = z * sC + (size_t)(r0 + hh * 8) * ldc + c0;
                    *(uint32_t*)(Chi + idx) = ph;
                    *(uint32_t*)(Clo + idx) = pl;
                }
            } else if (EM == 2) {
                float2 bv = *(const float2*)(bias + c0);
                float* dst = Cf + z * sC;
                *(float2*)(dst + (size_t)r0 * ldc + c0) =
                    make_float2(fmaxf(p[0] + bv.x, 0.f), fmaxf(p[1] + bv.y, 0.f));
                *(float2*)(dst + (size_t)(r0 + 8) * ldc + c0) =
                    make_float2(fmaxf(p[2] + bv.x, 0.f), fmaxf(p[3] + bv.y, 0.f));
            }
        }
    }

    // ---------------- epilogue: per-column partial softmax stats ----------
    if (EM == 3) {
        float* sred = (float*)smem;          // [2][128] maxes, then [2][128] sums at +256
        float cm[4][2];
        #pragma unroll
        for (int ni = 0; ni < 4; ni++)
            #pragma unroll
            for (int q = 0; q < 2; q++) {
                float m = -1e30f;
                #pragma unroll
                for (int mi = 0; mi < 4; mi++)
                    m = fmaxf(m, fmaxf(acc[mi][ni][q], acc[mi][ni][q + 2]));
                #pragma unroll
                for (int mk = 4; mk <= 16; mk <<= 1)
                    m = fmaxf(m, __shfl_xor_sync(0xFFFFFFFFu, m, mk));
                cm[ni][q] = m;
            }
        if (lane < 4) {
            #pragma unroll
            for (int ni = 0; ni < 4; ni++)
                #pragma unroll
                for (int q = 0; q < 2; q++)
                    sred[wM * 128 + wN * 32 + ni * 8 + (lane & 3) * 2 + q] = cm[ni][q];
        }
        __syncthreads();
        float cs[4][2];
        #pragma unroll
        for (int ni = 0; ni < 4; ni++)
            #pragma unroll
            for (int q = 0; q < 2; q++) {
                const int col = wN * 32 + ni * 8 + (lane & 3) * 2 + q;
                float fm = fmaxf(sred[col], sred[128 + col]);
                float s = 0.f;
                #pragma unroll
                for (int mi = 0; mi < 4; mi++)
                    s += __expf(acc[mi][ni][q] - fm) + __expf(acc[mi][ni][q + 2] - fm);
                #pragma unroll
                for (int mk = 4; mk <= 16; mk <<= 1)
                    s += __shfl_xor_sync(0xFFFFFFFFu, s, mk);
                cs[ni][q] = s;
            }
        if (lane < 4) {
            #pragma unroll
            for (int ni = 0; ni < 4; ni++)
                #pragma unroll
                for (int q = 0; q < 2; q++)
                    sred[256 + wM * 128 + wN * 32 + ni * 8 + (lane & 3) * 2 + q] = cs[ni][q];
        }
        __syncthreads();
        if (tid < 128) {
            const int col = tid;
            float m0 = sred[col], m1 = sred[128 + col];
            float fm = fmaxf(m0, m1);
            float s = sred[256 + col] + sred[384 + col];
            size_t idx = ((size_t)z * 16 + blockIdx.y) * L_ + nT + col;
            Pmax[idx] = fm;
            Psum[idx] = s;
        }
    }
}

// ======================= small prep kernels ================================
__global__ void split_k(const float* __restrict__ x, __nv_bfloat16* __restrict__ hi,
                        __nv_bfloat16* __restrict__ lo, int n4)
{
    for (int i = blockIdx.x * blockDim.x + threadIdx.x; i < n4; i += gridDim.x * blockDim.x) {
        float4 v = ((const float4*)x)[i];
        uint2 h, l; pack_split4(v, h, l);
        ((uint2*)hi)[i] = h;
        ((uint2*)lo)[i] = l;
    }
}

__global__ void transpose_split(const float* __restrict__ G,
                                __nv_bfloat16* __restrict__ Thi, __nv_bfloat16* __restrict__ Tlo)
{
    __shared__ float t[32][33];
    const int j0 = blockIdx.x * 32, h0 = blockIdx.y * 32, b = blockIdx.z;
    const float* Gb = G + (size_t)b * L_ * H_;
    #pragma unroll
    for (int r = 0; r < 4; r++) {
        int row = threadIdx.y + r * 8;
        t[row][threadIdx.x] = Gb[(size_t)(j0 + row) * H_ + h0 + threadIdx.x];
    }
    __syncthreads();
    __nv_bfloat16* Th = Thi + (size_t)b * H_ * L_;
    __nv_bfloat16* Tl = Tlo + (size_t)b * H_ * L_;
    #pragma unroll
    for (int r = 0; r < 4; r++) {
        int hr = threadIdx.y + r * 8;
        float x = t[threadIdx.x][hr];
        __nv_bfloat16 h, l; split1(x, h, l);
        Th[(size_t)(h0 + hr) * L_ + j0 + threadIdx.x] = h;
        Tl[(size_t)(h0 + hr) * L_ + j0 + threadIdx.x] = l;
    }
}

// combine 16 per-tile partials per column -> M, 1/D
__global__ void reduce_stats(const float* __restrict__ Pmax, const float* __restrict__ Psum,
                             float* __restrict__ Mo, float* __restrict__ IDo)
{
    const int idx = blockIdx.x * blockDim.x + threadIdx.x;   // z*2048 + col
    const int z = idx >> 11, col = idx & (L_ - 1);
    const size_t base = (size_t)z * 16 * L_ + col;
    float M = -1e30f;
    float pm[16];
    #pragma unroll
    for (int t = 0; t < 16; t++) {
        pm[t] = Pmax[base + (size_t)t * L_];
        M = fmaxf(M, pm[t]);
    }
    float D = 0.f;
    #pragma unroll
    for (int t = 0; t < 16; t++)
        D += Psum[base + (size_t)t * L_] * __expf(pm[t] - M);
    Mo[idx] = M;
    IDo[idx] = 1.0f / D;
}

// ===========================================================================
extern "C" void kernel_launch(void* const* d_in, const int* in_sizes, int n_in,
                              void* d_out, int out_size)
{
    const float* g     = (const float*)d_in[0];
    const float* WP    = (const float*)d_in[1];
    const float* W_out = (const float*)d_in[2];
    const float* b_out = (const float*)d_in[3];
    float* out = (float*)d_out;

    float *S, *C, *M, *ID, *Pm, *Ps;
    __nv_bfloat16 *gHi, *gLo, *gTHi, *gTLo, *WhHi, *WhLo;
    __nv_bfloat16 *WPHi, *WPLo, *WoHi, *WoLo;
    cudaGetSymbolAddress((void**)&S, d_S);
    cudaGetSymbolAddress((void**)&C, d_C);
    cudaGetSymbolAddress((void**)&M, d_M);
    cudaGetSymbolAddress((void**)&ID, d_ID);
    cudaGetSymbolAddress((void**)&Pm, d_Pmax);
    cudaGetSymbolAddress((void**)&Ps, d_Psum);
    cudaGetSymbolAddress((void**)&gHi, d_gHi);   cudaGetSymbolAddress((void**)&gLo, d_gLo);
    cudaGetSymbolAddress((void**)&gTHi, d_gTHi); cudaGetSymbolAddress((void**)&gTLo, d_gTLo);
    cudaGetSymbolAddress((void**)&WhHi, d_WhHi); cudaGetSymbolAddress((void**)&WhLo, d_WhLo);
    cudaGetSymbolAddress((void**)&WPHi, d_WPHi); cudaGetSymbolAddress((void**)&WPLo, d_WPLo);
    cudaGetSymbolAddress((void**)&WoHi, d_WoHi); cudaGetSymbolAddress((void**)&WoLo, d_WoLo);

    cudaFuncSetAttribute(mma_gemm<0,1>, cudaFuncAttributeMaxDynamicSharedMemorySize, GEMM_SMEM);
    cudaFuncSetAttribute(mma_gemm<0,3>, cudaFuncAttributeMaxDynamicSharedMemorySize, GEMM_SMEM);
    cudaFuncSetAttribute(mma_gemm<1,0>, cudaFuncAttributeMaxDynamicSharedMemorySize, GEMM_SMEM);
    cudaFuncSetAttribute(mma_gemm<2,2>, cudaFuncAttributeMaxDynamicSharedMemorySize, GEMM_SMEM);

    // 0) split inputs to hi/lo bf16
    split_k<<<2048, 256>>>(g, gHi, gLo, B_ * L_ * H_ / 4);
    split_k<<<64, 256>>>(WP, WPHi, WPLo, H_ * H_ / 4);
    split_k<<<192, 256>>>(W_out, WoHi, WoLo, H_ * 3 * H_ / 4);
    transpose_split<<<dim3(L_ / 32, H_ / 32, B_), dim3(32, 8)>>>(g, gTHi, gTLo);

    // 1) Wh = g @ WP^T  (16384 x 256 x 256) -> split bf16
    mma_gemm<0,1><<<dim3(2, 128, 1), 256, GEMM_SMEM>>>(
        gHi, gLo, nullptr, nullptr, nullptr, nullptr, WPHi, WPLo,
        nullptr, WhHi, WhLo, nullptr, nullptr, nullptr,
        H_, H_, 0, H_, H_, 0, 0, 0);

    // 2) S[b] = Wh[b] @ g[b]^T  -> fp32 + per-tile column stats
    mma_gemm<0,3><<<dim3(16, 16, B_), 256, GEMM_SMEM>>>(
        WhHi, WhLo, nullptr, nullptr, nullptr, nullptr, gHi, gLo,
        S, nullptr, nullptr, nullptr, Pm, Ps,
        H_, H_, 0, H_, L_, (long)L_ * H_, (long)L_ * H_, (long)L_ * L_);

    // 3) combine partials -> M, 1/D
    reduce_stats<<<(B_ * L_) / 256, 256>>>(Pm, Ps, M, ID);

    // 4) c[b] = softmax(S)[b] @ g[b]  (A produced in-kernel from S,M,ID)
    mma_gemm<1,0><<<dim3(2, 16, B_), 256, GEMM_SMEM>>>(
        nullptr, nullptr, S, nullptr, M, ID, gTHi, gTLo,
        C, nullptr, nullptr, nullptr, nullptr, nullptr,
        L_, 0, L_, L_, H_, (long)L_ * L_, (long)H_ * L_, (long)L_ * H_);

    // 5) out = relu(cat(g, c, g*c) @ W_out^T + b)  (A produced in-kernel)
    mma_gemm<2,2><<<dim3(2, 128, 1), 256, GEMM_SMEM>>>(
        nullptr, nullptr, g, C, nullptr, nullptr, WoHi, WoLo,
        out, nullptr, nullptr, b_out, nullptr, nullptr,
        3 * H_, 0, H_, 3 * H_, H_, 0, 0, 0);
}

// round 7
// speedup vs baseline: 5.5651x; 1.2335x over previous
#include <cuda_runtime.h>
#include <cuda_fp16.h>
#include <cstdint>
#include <math.h>

#define B_ 8
#define L_ 2048
#define H_ 256

// ======================= PTX helpers (baseline ISA only) ===================
__device__ __forceinline__ uint32_t smem_u32(const void* p) {
    uint32_t a;
    asm("{ .reg .u64 t; cvta.to.shared.u64 t, %1; cvt.u32.u64 %0, t; }" : "=r"(a) : "l"(p));
    return a;
}
#define CP_ASYNC16(dst, src) \
    asm volatile("cp.async.cg.shared.global [%0], [%1], 16;" :: "r"(dst), "l"(src) : "memory")
#define CP_COMMIT() asm volatile("cp.async.commit_group;" ::: "memory")
#define CP_WAIT1()  asm volatile("cp.async.wait_group 1;" ::: "memory")
#define CP_WAIT0()  asm volatile("cp.async.wait_group 0;" ::: "memory")

#define LDSM_X4(r0, r1, r2, r3, a) \
    asm volatile("ldmatrix.sync.aligned.m8n8.x4.shared.b16 {%0,%1,%2,%3}, [%4];" \
        : "=r"(r0), "=r"(r1), "=r"(r2), "=r"(r3) : "r"(a))

#define MMA_F16(d, a, b) \
    asm volatile("mma.sync.aligned.m16n8k16.row.col.f32.f16.f16.f32 " \
        "{%0,%1,%2,%3}, {%4,%5,%6,%7}, {%8,%9}, {%0,%1,%2,%3};" \
        : "+f"((d)[0]), "+f"((d)[1]), "+f"((d)[2]), "+f"((d)[3]) \
        : "r"((a)[0]), "r"((a)[1]), "r"((a)[2]), "r"((a)[3]), "r"((b)[0]), "r"((b)[1]))

__device__ __forceinline__ uint32_t swz(uint32_t o) { return o ^ ((o >> 3) & 0x70); }

// ======================= scratch (device globals) ==========================
__device__ float   d_S[(size_t)B_ * L_ * L_];        // 128 MB
__device__ __half  d_gHi[B_ * L_ * H_], d_gLo[B_ * L_ * H_];
__device__ __half  d_gTsHi[B_ * H_ * L_], d_gTsLo[B_ * H_ * L_];   // ID-scaled g^T
__device__ __half  d_WhHi[B_ * L_ * H_], d_WhLo[B_ * L_ * H_];
__device__ __half  d_WPHi[H_ * H_], d_WPLo[H_ * H_];
__device__ __half  d_WoHi[H_ * 3 * H_], d_WoLo[H_ * 3 * H_];
__device__ float   d_C[B_ * L_ * H_];
__device__ float   d_M[B_ * L_], d_ID[B_ * L_];
__device__ float   d_Pmax[B_ * 16 * L_], d_Psum[B_ * 16 * L_];

__device__ __forceinline__ void split1h(float x, __half& h, __half& l) {
    h = __float2half_rn(x);
    l = __float2half_rn(x - __half2float(h));
}
__device__ __forceinline__ void pack_split4h(float4 v, uint2& hi, uint2& lo) {
    __half h[4], l[4];
    split1h(v.x, h[0], l[0]); split1h(v.y, h[1], l[1]);
    split1h(v.z, h[2], l[2]); split1h(v.w, h[3], l[3]);
    hi = *(uint2*)h; lo = *(uint2*)l;
}
__device__ __forceinline__ uint2 pack4h(float4 v) {
    __half h[4];
    h[0] = __float2half_rn(v.x); h[1] = __float2half_rn(v.y);
    h[2] = __float2half_rn(v.z); h[3] = __float2half_rn(v.w);
    return *(uint2*)h;
}

// ======================= 3-pass split-fp16 NT GEMM (128x128) ===============
// D = (Ah+Al)(Bh+Bl)^T via HH+HL+LH. 256 thr, 8 warps (2M x 4N), K-chunk 64.
// SMEM stage 64KB {Ah,Al,Bh,Bl} x2 = 128KB.
// EM 1: split-fp16 store | EM 3: fp32 store + per-tile column softmax stats
static constexpr int GEMM3_SMEM = 2 * 65536;

__device__ __forceinline__ void tile128(const __half* __restrict__ src, int ld,
                                        uint32_t dstBase, int tid) {
    #pragma unroll
    for (int s = 0; s < 4; s++) {
        int slot = tid + s * 256;
        int row = slot >> 3;
        int cb = (slot & 7) * 16;
        CP_ASYNC16(dstBase + swz(row * 128 + cb), (const char*)src + (size_t)row * ld * 2 + cb);
    }
}

template <int EM>
__global__ __launch_bounds__(256)
void gemm3p(const __half* __restrict__ Ahi, const __half* __restrict__ Alo,
            const __half* __restrict__ Bhi, const __half* __restrict__ Blo,
            float* __restrict__ Cf, __half* __restrict__ Chi, __half* __restrict__ Clo,
            float* __restrict__ Pmax, float* __restrict__ Psum,
            int K, int lda, int ldb, int ldc, long sA, long sB, long sC)
{
    extern __shared__ char smem[];
    const uint32_t sb = smem_u32(smem);
    const int tid = threadIdx.x;
    const int lane = tid & 31, wid = tid >> 5;
    const int wM = wid >> 2, wN = wid & 3;
    const int mT = blockIdx.y * 128, nT = blockIdx.x * 128;
    const long z = blockIdx.z;

    const __half* Ah = Ahi + z * sA + (long)mT * lda;
    const __half* Al = Alo + z * sA + (long)mT * lda;
    const __half* Bh = Bhi + z * sB + (long)nT * ldb;
    const __half* Bl = Blo + z * sB + (long)nT * ldb;
    const int NC = K >> 6;

    tile128(Ah, lda, sb,         tid);
    tile128(Al, lda, sb + 16384, tid);
    tile128(Bh, ldb, sb + 32768, tid);
    tile128(Bl, ldb, sb + 49152, tid);
    CP_COMMIT();

    float acc[4][4][4] = {};
    const int aRow = lane & 15;
    const int aColB = (lane >> 4) * 16;
    const int bRowP = ((lane >> 4) & 1) * 8 + (lane & 7);     // x4-pair row
    const int bColB = ((lane >> 3) & 1) * 16;

    for (int c = 0; c < NC; c++) {
        if (c + 1 < NC) {
            const uint32_t o1 = sb + ((c + 1) & 1) * 65536;
            const int k1 = (c + 1) * 64;
            tile128(Ah + k1, lda, o1,         tid);
            tile128(Al + k1, lda, o1 + 16384, tid);
            tile128(Bh + k1, ldb, o1 + 32768, tid);
            tile128(Bl + k1, ldb, o1 + 49152, tid);
            CP_COMMIT();
            CP_WAIT1();
        } else {
            CP_WAIT0();
        }
        __syncthreads();

        const uint32_t o = sb + (c & 1) * 65536;
        #pragma unroll
        for (int ks = 0; ks < 4; ks++) {
            const int kb = ks * 32;
            uint32_t rah[4][4], ral[4][4], rbh[4][2], rbl[4][2];
            #pragma unroll
            for (int mi = 0; mi < 4; mi++) {
                uint32_t off = swz((uint32_t)(wM * 64 + mi * 16 + aRow) * 128 + kb + aColB);
                LDSM_X4(rah[mi][0], rah[mi][1], rah[mi][2], rah[mi][3], o + off);
                LDSM_X4(ral[mi][0], ral[mi][1], ral[mi][2], ral[mi][3], o + 16384 + off);
            }
            #pragma unroll
            for (int p = 0; p < 2; p++) {
                uint32_t off = swz((uint32_t)(wN * 32 + p * 16 + bRowP) * 128 + kb + bColB);
                LDSM_X4(rbh[2 * p][0], rbh[2 * p][1], rbh[2 * p + 1][0], rbh[2 * p + 1][1],
                        o + 32768 + off);
                LDSM_X4(rbl[2 * p][0], rbl[2 * p][1], rbl[2 * p + 1][0], rbl[2 * p + 1][1],
                        o + 49152 + off);
            }
            #pragma unroll
            for (int mi = 0; mi < 4; mi++)
                #pragma unroll
                for (int ni = 0; ni < 4; ni++) {
                    MMA_F16(acc[mi][ni], rah[mi], rbh[ni]);
                    MMA_F16(acc[mi][ni], rah[mi], rbl[ni]);
                    MMA_F16(acc[mi][ni], ral[mi], rbh[ni]);
                }
        }
        __syncthreads();
    }

    const int rBase = mT + wM * 64 + (lane >> 2);
    const int cBase = nT + wN * 32 + (lane & 3) * 2;
    #pragma unroll
    for (int mi = 0; mi < 4; mi++)
        #pragma unroll
        for (int ni = 0; ni < 4; ni++) {
            const int r0 = rBase + mi * 16;
            const int c0 = cBase + ni * 8;
            float* p = acc[mi][ni];
            if (EM == 3) {
                float* dst = Cf + z * sC;
                *(float2*)(dst + (size_t)r0 * ldc + c0) = make_float2(p[0], p[1]);
                *(float2*)(dst + (size_t)(r0 + 8) * ldc + c0) = make_float2(p[2], p[3]);
            } else {
                #pragma unroll
                for (int hh = 0; hh < 2; hh++) {
                    __half h0, l0, h1, l1;
                    split1h(p[hh * 2 + 0], h0, l0);
                    split1h(p[hh * 2 + 1], h1, l1);
                    uint32_t ph = ((uint32_t)*(uint16_t*)&h1 << 16) | *(uint16_t*)&h0;
                    uint32_t pl = ((uint32_t)*(uint16_t*)&l1 << 16) | *(uint16_t*)&l0;
                    size_t idx = z * sC + (size_t)(r0 + hh * 8) * ldc + c0;
                    *(uint32_t*)(Chi + idx) = ph;
                    *(uint32_t*)(Clo + idx) = pl;
                }
            }
        }

    if (EM == 3) {
        float* sred = (float*)smem;
        float cm[4][2];
        #pragma unroll
        for (int ni = 0; ni < 4; ni++)
            #pragma unroll
            for (int q = 0; q < 2; q++) {
                float m = -1e30f;
                #pragma unroll
                for (int mi = 0; mi < 4; mi++)
                    m = fmaxf(m, fmaxf(acc[mi][ni][q], acc[mi][ni][q + 2]));
                #pragma unroll
                for (int mk = 4; mk <= 16; mk <<= 1)
                    m = fmaxf(m, __shfl_xor_sync(0xFFFFFFFFu, m, mk));
                cm[ni][q] = m;
            }
        if (lane < 4)
            #pragma unroll
            for (int ni = 0; ni < 4; ni++)
                #pragma unroll
                for (int q = 0; q < 2; q++)
                    sred[wM * 128 + wN * 32 + ni * 8 + (lane & 3) * 2 + q] = cm[ni][q];
        __syncthreads();
        float cs[4][2];
        #pragma unroll
        for (int ni = 0; ni < 4; ni++)
            #pragma unroll
            for (int q = 0; q < 2; q++) {
                const int col = wN * 32 + ni * 8 + (lane & 3) * 2 + q;
                float fm = fmaxf(sred[col], sred[128 + col]);
                float s = 0.f;
                #pragma unroll
                for (int mi = 0; mi < 4; mi++)
                    s += __expf(acc[mi][ni][q] - fm) + __expf(acc[mi][ni][q + 2] - fm);
                #pragma unroll
                for (int mk = 4; mk <= 16; mk <<= 1)
                    s += __shfl_xor_sync(0xFFFFFFFFu, s, mk);
                cs[ni][q] = s;
            }
        if (lane < 4)
            #pragma unroll
            for (int ni = 0; ni < 4; ni++)
                #pragma unroll
                for (int q = 0; q < 2; q++)
                    sred[256 + wM * 128 + wN * 32 + ni * 8 + (lane & 3) * 2 + q] = cs[ni][q];
        __syncthreads();
        if (tid < 128) {
            float fm = fmaxf(sred[tid], sred[128 + tid]);
            float s = sred[256 + tid] + sred[384 + tid];
            size_t idx = ((size_t)z * 16 + blockIdx.y) * L_ + nT + tid;
            Pmax[idx] = fm;
            Psum[idx] = s;
        }
    }
}

// ======================= 2-pass fp16 NT GEMM (128x256) =====================
// D = A(Bh+Bl)^T, A single fp16 produced in-kernel. 512 thr, 16 warps (4Mx4N),
// warp tile 32x64. SMEM stage 80KB {A:16K, Bh:32K, Bl:32K} x2 = 160KB.
// AM 1: A = exp(S - M_j)   | AM 2: A = cat(g, C, g*C) segments
// EM 0: fp32 store         | EM 2: bias + relu fp32
static constexpr int GEMM2_SMEM = 2 * 81920;

__device__ __forceinline__ void tile256(const __half* __restrict__ src, int ld,
                                        uint32_t dstBase, int tid) {
    #pragma unroll
    for (int s = 0; s < 4; s++) {
        int slot = tid + s * 512;
        int row = slot >> 3;
        int cb = (slot & 7) * 16;
        CP_ASYNC16(dstBase + swz(row * 128 + cb), (const char*)src + (size_t)row * ld * 2 + cb);
    }
}

template <int AM, int EM>
__global__ __launch_bounds__(512)
void gemm2p(const float* __restrict__ Af1, const float* __restrict__ Af2,
            const float* __restrict__ Mst,
            const __half* __restrict__ Bhi, const __half* __restrict__ Blo,
            float* __restrict__ Cf, const float* __restrict__ bias,
            int K, int ldaF, int ldb, int ldc, long sA, long sB, long sC)
{
    extern __shared__ char smem[];
    const uint32_t sb = smem_u32(smem);
    const int tid = threadIdx.x;
    const int lane = tid & 31, wid = tid >> 5;
    const int wM = wid >> 2, wN = wid & 3;
    const int mT = blockIdx.y * 128;
    const long z = blockIdx.z;

    const __half* Bh = Bhi + z * sB;
    const __half* Bl = Blo + z * sB;
    const int NC = K >> 6;

    const int c4 = tid & 15, rT = tid >> 5;        // unused placeholder
    const int rA = tid >> 4;                        // 0..31, rows rA + s*32
    float4 ra[4];
    const float* Sg = (AM == 1) ? (Af1 + z * sA + (size_t)mT * ldaF) : nullptr;

    if (AM == 1) {
        #pragma unroll
        for (int s = 0; s < 4; s++)
            ra[s] = *(const float4*)(Sg + (size_t)(rA + s * 32) * ldaF + c4 * 4);
    }
    tile256(Bh, ldb, sb + 16384, tid);
    tile256(Bl, ldb, sb + 49152, tid);
    CP_COMMIT();

    float acc[2][8][4] = {};
    const int aRow = lane & 15;
    const int aColB = (lane >> 4) * 16;
    const int bRowP = ((lane >> 4) & 1) * 8 + (lane & 7);
    const int bColB = ((lane >> 3) & 1) * 16;

    for (int c = 0; c < NC; c++) {
        const int buf = c & 1;
        const uint32_t o = sb + buf * 81920;

        // ---- produce A(c) ----
        if (AM == 1) {
            const int k0 = c * 64;
            float4 mv = *(const float4*)(Mst + z * L_ + k0 + c4 * 4);
            #pragma unroll
            for (int s = 0; s < 4; s++) {
                float4 v = ra[s];
                v.x = __expf(v.x - mv.x);
                v.y = __expf(v.y - mv.y);
                v.z = __expf(v.z - mv.z);
                v.w = __expf(v.w - mv.w);
                uint32_t off = swz((uint32_t)(rA + s * 32) * 128 + c4 * 8);
                *(uint2*)(smem + buf * 81920 + off) = pack4h(v);
            }
        } else {
            const int k0 = c * 64;
            const int seg = k0 >> 8;
            const int hc = (k0 & 255) + c4 * 4;
            #pragma unroll
            for (int s = 0; s < 4; s++) {
                const size_t mrow = (size_t)(mT + rA + s * 32);
                float4 v;
                if (seg == 0) v = *(const float4*)(Af1 + mrow * ldaF + hc);
                else if (seg == 1) v = *(const float4*)(Af2 + mrow * ldaF + hc);
                else {
                    float4 g4 = *(const float4*)(Af1 + mrow * ldaF + hc);
                    float4 cc = *(const float4*)(Af2 + mrow * ldaF + hc);
                    v = make_float4(g4.x * cc.x, g4.y * cc.y, g4.z * cc.z, g4.w * cc.w);
                }
                uint32_t off = swz((uint32_t)(rA + s * 32) * 128 + c4 * 8);
                *(uint2*)(smem + buf * 81920 + off) = pack4h(v);
            }
        }

        // ---- stage chunk c+1 ----
        if (c + 1 < NC) {
            const uint32_t o1 = sb + ((c + 1) & 1) * 81920;
            const int k1 = (c + 1) * 64;
            if (AM == 1) {
                #pragma unroll
                for (int s = 0; s < 4; s++)
                    ra[s] = *(const float4*)(Sg + (size_t)(rA + s * 32) * ldaF + k1 + c4 * 4);
            }
            tile256(Bh + k1, ldb, o1 + 16384, tid);
            tile256(Bl + k1, ldb, o1 + 49152, tid);
            CP_COMMIT();
            CP_WAIT1();
        } else {
            CP_WAIT0();
        }
        __syncthreads();

        #pragma unroll
        for (int ks = 0; ks < 4; ks++) {
            const int kb = ks * 32;
            uint32_t rah[2][4];
            #pragma unroll
            for (int mi = 0; mi < 2; mi++) {
                uint32_t off = swz((uint32_t)(wM * 32 + mi * 16 + aRow) * 128 + kb + aColB);
                LDSM_X4(rah[mi][0], rah[mi][1], rah[mi][2], rah[mi][3], o + off);
            }
            #pragma unroll
            for (int p = 0; p < 4; p++) {
                uint32_t bh[4], bl[4];
                uint32_t off = swz((uint32_t)(wN * 64 + p * 16 + bRowP) * 128 + kb + bColB);
                LDSM_X4(bh[0], bh[1], bh[2], bh[3], o + 16384 + off);
                LDSM_X4(bl[0], bl[1], bl[2], bl[3], o + 49152 + off);
                #pragma unroll
                for (int mi = 0; mi < 2; mi++) {
                    MMA_F16(acc[mi][2 * p],     rah[mi], bh);
                    MMA_F16(acc[mi][2 * p],     rah[mi], bl);
                    MMA_F16(acc[mi][2 * p + 1], rah[mi], bh + 2);
                    MMA_F16(acc[mi][2 * p + 1], rah[mi], bl + 2);
                }
            }
        }
        __syncthreads();
    }

    const int rBase = mT + wM * 32 + (lane >> 2);
    const int cBase = wN * 64 + (lane & 3) * 2;
    #pragma unroll
    for (int mi = 0; mi < 2; mi++)
        #pragma unroll
        for (int ni = 0; ni < 8; ni++) {
            const int r0 = rBase + mi * 16;
            const int c0 = cBase + ni * 8;
            float* p = acc[mi][ni];
            if (EM == 0) {
                float* dst = Cf + z * sC;
                *(float2*)(dst + (size_t)r0 * ldc + c0) = make_float2(p[0], p[1]);
                *(float2*)(dst + (size_t)(r0 + 8) * ldc + c0) = make_float2(p[2], p[3]);
            } else {
                float2 bv = *(const float2*)(bias + c0);
                float* dst = Cf + z * sC;
                *(float2*)(dst + (size_t)r0 * ldc + c0) =
                    make_float2(fmaxf(p[0] + bv.x, 0.f), fmaxf(p[1] + bv.y, 0.f));
                *(float2*)(dst + (size_t)(r0 + 8) * ldc + c0) =
                    make_float2(fmaxf(p[2] + bv.x, 0.f), fmaxf(p[3] + bv.y, 0.f));
            }
        }
}

// ======================= prep / softmax kernels ============================
__global__ void split_k(const float* __restrict__ x, __half* __restrict__ hi,
                        __half* __restrict__ lo, int n4)
{
    for (int i = blockIdx.x * blockDim.x + threadIdx.x; i < n4; i += gridDim.x * blockDim.x) {
        float4 v = ((const float4*)x)[i];
        uint2 h, l; pack_split4h(v, h, l);
        ((uint2*)hi)[i] = h;
        ((uint2*)lo)[i] = l;
    }
}

// gTs[b, h, j] = ID[b,j] * g[b, j, h], split fp16
__global__ void transpose_scale_split(const float* __restrict__ G, const float* __restrict__ ID,
                                      __half* __restrict__ Thi, __half* __restrict__ Tlo)
{
    __shared__ float t[32][33];
    const int j0 = blockIdx.x * 32, h0 = blockIdx.y * 32, b = blockIdx.z;
    const float* Gb = G + (size_t)b * L_ * H_;
    #pragma unroll
    for (int r = 0; r < 4; r++) {
        int row = threadIdx.y + r * 8;
        t[row][threadIdx.x] = Gb[(size_t)(j0 + row) * H_ + h0 + threadIdx.x]
                              * ID[b * L_ + j0 + row];
    }
    __syncthreads();
    __half* Th = Thi + (size_t)b * H_ * L_;
    __half* Tl = Tlo + (size_t)b * H_ * L_;
    #pragma unroll
    for (int r = 0; r < 4; r++) {
        int hr = threadIdx.y + r * 8;
        float x = t[threadIdx.x][hr];
        __half h, l; split1h(x, h, l);
        Th[(size_t)(h0 + hr) * L_ + j0 + threadIdx.x] = h;
        Tl[(size_t)(h0 + hr) * L_ + j0 + threadIdx.x] = l;
    }
}

__global__ void reduce_stats(const float* __restrict__ Pmax, const float* __restrict__ Psum,
                             float* __restrict__ Mo, float* __restrict__ IDo)
{
    const int idx = blockIdx.x * blockDim.x + threadIdx.x;
    const size_t base = ((size_t)(idx >> 11) * 16) * L_ + (idx & (L_ - 1));
    float M = -1e30f;
    float pm[16];
    #pragma unroll
    for (int t = 0; t < 16; t++) {
        pm[t] = Pmax[base + (size_t)t * L_];
        M = fmaxf(M, pm[t]);
    }
    float D = 0.f;
    #pragma unroll
    for (int t = 0; t < 16; t++)
        D += Psum[base + (size_t)t * L_] * __expf(pm[t] - M);
    Mo[idx] = M;
    IDo[idx] = 1.0f / D;
}

// ===========================================================================
extern "C" void kernel_launch(void* const* d_in, const int* in_sizes, int n_in,
                              void* d_out, int out_size)
{
    const float* g     = (const float*)d_in[0];
    const float* WP    = (const float*)d_in[1];
    const float* W_out = (const float*)d_in[2];
    const float* b_out = (const float*)d_in[3];
    float* out = (float*)d_out;

    float *S, *C, *M, *ID, *Pm, *Ps;
    __half *gHi, *gLo, *gTsHi, *gTsLo, *WhHi, *WhLo, *WPHi, *WPLo, *WoHi, *WoLo;
    cudaGetSymbolAddress((void**)&S, d_S);
    cudaGetSymbolAddress((void**)&C, d_C);
    cudaGetSymbolAddress((void**)&M, d_M);
    cudaGetSymbolAddress((void**)&ID, d_ID);
    cudaGetSymbolAddress((void**)&Pm, d_Pmax);
    cudaGetSymbolAddress((void**)&Ps, d_Psum);
    cudaGetSymbolAddress((void**)&gHi, d_gHi);     cudaGetSymbolAddress((void**)&gLo, d_gLo);
    cudaGetSymbolAddress((void**)&gTsHi, d_gTsHi); cudaGetSymbolAddress((void**)&gTsLo, d_gTsLo);
    cudaGetSymbolAddress((void**)&WhHi, d_WhHi);   cudaGetSymbolAddress((void**)&WhLo, d_WhLo);
    cudaGetSymbolAddress((void**)&WPHi, d_WPHi);   cudaGetSymbolAddress((void**)&WPLo, d_WPLo);
    cudaGetSymbolAddress((void**)&WoHi, d_WoHi);   cudaGetSymbolAddress((void**)&WoLo, d_WoLo);

    cudaFuncSetAttribute(gemm3p<1>, cudaFuncAttributeMaxDynamicSharedMemorySize, GEMM3_SMEM);
    cudaFuncSetAttribute(gemm3p<3>, cudaFuncAttributeMaxDynamicSharedMemorySize, GEMM3_SMEM);
    cudaFuncSetAttribute(gemm2p<1,0>, cudaFuncAttributeMaxDynamicSharedMemorySize, GEMM2_SMEM);
    cudaFuncSetAttribute(gemm2p<2,2>, cudaFuncAttributeMaxDynamicSharedMemorySize, GEMM2_SMEM);

    // 0) split inputs to fp16 hi/lo
    split_k<<<2048, 256>>>(g, gHi, gLo, B_ * L_ * H_ / 4);
    split_k<<<64, 256>>>(WP, WPHi, WPLo, H_ * H_ / 4);
    split_k<<<192, 256>>>(W_out, WoHi, WoLo, H_ * 3 * H_ / 4);

    // 1) Wh = g @ WP^T  (3-pass, split-fp16 out)
    gemm3p<1><<<dim3(2, 128, 1), 256, GEMM3_SMEM>>>(
        gHi, gLo, WPHi, WPLo, nullptr, WhHi, WhLo, nullptr, nullptr,
        H_, H_, H_, H_, 0, 0, 0);

    // 2) S[b] = Wh[b] @ g[b]^T  (3-pass, fp32 + column stats)
    gemm3p<3><<<dim3(16, 16, B_), 256, GEMM3_SMEM>>>(
        WhHi, WhLo, gHi, gLo, S, nullptr, nullptr, Pm, Ps,
        H_, H_, H_, L_, (long)L_ * H_, (long)L_ * H_, (long)L_ * L_);

    // 3) combine partials -> M, 1/D
    reduce_stats<<<(B_ * L_) / 256, 256>>>(Pm, Ps, M, ID);

    // 4) gTs = (ID_j * g)^T split fp16
    transpose_scale_split<<<dim3(L_ / 32, H_ / 32, B_), dim3(32, 8)>>>(g, ID, gTsHi, gTsLo);

    // 5) c[b] = exp(S - M) @ gTs^T  (2-pass, A = u fp16 in-kernel)
    gemm2p<1,0><<<dim3(1, 16, B_), 512, GEMM2_SMEM>>>(
        S, nullptr, M, gTsHi, gTsLo, C, nullptr,
        L_, L_, L_, H_, (long)L_ * L_, (long)H_ * L_, (long)L_ * H_);

    // 6) out = relu(cat(g, c, g*c) @ W_out^T + b)  (2-pass, A built in-kernel)
    gemm2p<2,2><<<dim3(1, 128, 1), 512, GEMM2_SMEM>>>(
        g, C, nullptr, WoHi, WoLo, out, b_out,
        3 * H_, H_, 3 * H_, H_, 0, 0, 0);
}